// round 7
// baseline (speedup 1.0000x reference)
#include <cuda_runtime.h>
#include <cuda_bf16.h>

// Problem constants (fixed by the reference)
#define BATCH 524288
#define NFEAT 8
#define TPB 256
#define EPT 2

// Contraction tensor: out = sum_{a,b,c} T[a*9+b*3+c] * v0_a*v1_b*v2_c,
// v_i = (1, cos x_i, sin x_i)
__device__ float d_T[27];

// ---------------- Setup kernel (1 block, 64 threads) ----------------
// Builds V (variational unitary), M = Re(V^H Z0 V), then T via three
// branch-free separable sweeps. Runs overlapped with the main kernel's
// launch ramp thanks to PDL.
__global__ void vqc_setup_kernel(const float* __restrict__ w) {
    __shared__ float2 sc[18];
    __shared__ float Vr[8][8];
    __shared__ float Vi[8][8];
    __shared__ float Ms[8][8];
    __shared__ float Ps[48];
    __shared__ float Qs[36];

    const int tid = threadIdx.x;

    if (tid < 32) {
        if (tid < 18) {
            float c, s;
            __sincosf(0.5f * __ldg(&w[tid]), &s, &c);
            sc[tid] = make_float2(c, s);
        }
        __syncwarp();

        if (tid < 8) {
            float re[8], im[8];
#pragma unroll
            for (int k = 0; k < 8; k++) { re[k] = 0.0f; im[k] = 0.0f; }
            re[tid] = 1.0f;

#pragma unroll
            for (int l = 0; l < 3; l++) {
#pragma unroll
                for (int q = 0; q < 3; q++) {
                    const float2 y = sc[(l * 3 + q) * 2 + 0];
                    const float2 z = sc[(l * 3 + q) * 2 + 1];
                    const float cy = y.x, sy = y.y, cz = z.x, sz = z.y;
                    const int bit = 4 >> q;
#pragma unroll
                    for (int j = 0; j < 8; j++) {
                        if (j & bit) continue;
                        const int j1 = j | bit;
                        const float r0 = re[j],  i0 = im[j];
                        const float r1 = re[j1], i1 = im[j1];
                        // RY(th)
                        const float nr0 = cy * r0 - sy * r1;
                        const float ni0 = cy * i0 - sy * i1;
                        const float nr1 = sy * r0 + cy * r1;
                        const float ni1 = sy * i0 + cy * i1;
                        // RZ(ph)
                        re[j]  = cz * nr0 + sz * ni0;
                        im[j]  = cz * ni0 - sz * nr0;
                        re[j1] = cz * nr1 - sz * ni1;
                        im[j1] = cz * ni1 + sz * nr1;
                    }
                }
                // CNOT(0,1): control bit4, target bit2
#pragma unroll
                for (int j = 0; j < 8; j++) {
                    if ((j & 4) && !(j & 2)) {
                        const int j1 = j | 2;
                        float tmp;
                        tmp = re[j]; re[j] = re[j1]; re[j1] = tmp;
                        tmp = im[j]; im[j] = im[j1]; im[j1] = tmp;
                    }
                }
                // CNOT(1,2): control bit2, target bit1
#pragma unroll
                for (int j = 0; j < 8; j++) {
                    if ((j & 2) && !(j & 1)) {
                        const int j1 = j | 1;
                        float tmp;
                        tmp = re[j]; re[j] = re[j1]; re[j1] = tmp;
                        tmp = im[j]; im[j] = im[j1]; im[j1] = tmp;
                    }
                }
            }
#pragma unroll
            for (int r = 0; r < 8; r++) { Vr[r][tid] = re[r]; Vi[r][tid] = im[r]; }
        }
    }
    __syncthreads();

    if (tid < 64) {
        const int j = tid >> 3, k = tid & 7;
        float m = 0.0f;
#pragma unroll
        for (int r = 0; r < 8; r++) {
            const float zr = (r < 4) ? 1.0f : -1.0f;
            m += zr * (Vr[r][j] * Vr[r][k] + Vi[r][j] * Vi[r][k]);
        }
        Ms[j][k] = m;
    }
    __syncthreads();

    if (tid < 48) {  // Sweep 1 (qubit 0)
        const int a = tid >> 4, rem = tid & 15;
        const int r = rem >> 2, s = rem & 3;
        const float m00 = Ms[r][s],     m11 = Ms[4 + r][4 + s];
        const float m01 = Ms[r][4 + s], m10 = Ms[4 + r][s];
        float v;
        if (a == 0)      v = 0.5f * (m00 + m11);
        else if (a == 1) v = 0.5f * (m00 - m11);
        else             v = 0.5f * (m01 + m10);
        Ps[tid] = v;
    }
    __syncthreads();

    if (tid < 36) {  // Sweep 2 (qubit 1)
        const int a = tid / 12, rem = tid % 12;
        const int b = rem >> 2, j0 = (rem >> 1) & 1, k0 = rem & 1;
        const float* Pa = &Ps[a * 16];
        const float p00 = Pa[(0 * 2 + j0) * 4 + (0 * 2 + k0)];
        const float p11 = Pa[(1 * 2 + j0) * 4 + (1 * 2 + k0)];
        const float p01 = Pa[(0 * 2 + j0) * 4 + (1 * 2 + k0)];
        const float p10 = Pa[(1 * 2 + j0) * 4 + (0 * 2 + k0)];
        float v;
        if (b == 0)      v = 0.5f * (p00 + p11);
        else if (b == 1) v = 0.5f * (p00 - p11);
        else             v = 0.5f * (p01 + p10);
        Qs[tid] = v;
    }
    __syncthreads();

    if (tid < 27) {  // Sweep 3 (qubit 2) -> global T
        const int a = tid / 9, b = (tid / 3) % 3, c = tid % 3;
        const float* Qab = &Qs[a * 12 + b * 4];
        const float q00 = Qab[0], q01 = Qab[1], q10 = Qab[2], q11 = Qab[3];
        float v;
        if (c == 0)      v = 0.5f * (q00 + q11);
        else if (c == 1) v = 0.5f * (q00 - q11);
        else             v = 0.5f * (q01 + q10);
        d_T[tid] = v;
    }
}

// ---------------- Main kernel (PDL secondary) ----------------
__global__ void __launch_bounds__(TPB) vqc_main_kernel(
    const float4* __restrict__ x4, float* __restrict__ out) {

    const int base = blockIdx.x * (TPB * EPT) + threadIdx.x;

    // Issue batch loads FIRST — independent of the setup kernel's output.
    float4 xv[EPT];
#pragma unroll
    for (int e = 0; e < EPT; e++) {
        xv[e] = x4[2 * (base + e * TPB)];  // first 16B of each 32B row
    }

#if __CUDA_ARCH__ >= 900
    // Wait for the setup kernel (PDL): only now is d_T guaranteed visible.
    cudaGridDependencySynchronize();
#endif

    float T[27];
#pragma unroll
    for (int i = 0; i < 27; i++) T[i] = __ldg(&d_T[i]);

#pragma unroll
    for (int e = 0; e < EPT; e++) {
        float c0, s0, c1, s1, c2, s2;
        __sincosf(xv[e].x, &s0, &c0);
        __sincosf(xv[e].y, &s1, &c1);
        __sincosf(xv[e].z, &s2, &c2);

        float u[3];
#pragma unroll
        for (int a = 0; a < 3; a++) {
            float wb[3];
#pragma unroll
            for (int b = 0; b < 3; b++) {
                const float* Tb = &T[a * 9 + b * 3];
                wb[b] = Tb[0] + Tb[1] * c2 + Tb[2] * s2;
            }
            u[a] = wb[0] + wb[1] * c1 + wb[2] * s1;
        }
        out[base + e * TPB] = u[0] + u[1] * c0 + u[2] * s0;
    }
}

extern "C" void kernel_launch(void* const* d_in, const int* in_sizes, int n_in,
                              void* d_out, int out_size) {
    const float* x = (const float*)d_in[0];        // [BATCH, 8]
    const float* w = (const float*)d_in[1];        // [3, 3, 2]
    float* out = (float*)d_out;                    // [BATCH, 1]

    vqc_setup_kernel<<<1, 64>>>(w);

    const int nblocks = BATCH / (TPB * EPT);       // 1024

    // Launch main kernel with programmatic stream serialization (PDL):
    // its blocks may launch while the setup kernel is still running; the
    // in-kernel cudaGridDependencySynchronize() provides the ordering.
    cudaLaunchConfig_t cfg = {};
    cfg.gridDim = dim3(nblocks, 1, 1);
    cfg.blockDim = dim3(TPB, 1, 1);
    cfg.dynamicSmemBytes = 0;
    cfg.stream = 0;  // legacy default stream (same as <<<>>>), captured by harness

    cudaLaunchAttribute attr;
    attr.id = cudaLaunchAttributeProgrammaticStreamSerialization;
    attr.val.programmaticStreamSerializationAllowed = 1;
    cfg.attrs = &attr;
    cfg.numAttrs = 1;

    cudaError_t e = cudaLaunchKernelEx(&cfg, vqc_main_kernel,
                                       (const float4*)x, out);
    if (e != cudaSuccess) {
        // Fallback: plain stream-ordered launch (sync becomes a no-op).
        vqc_main_kernel<<<nblocks, TPB>>>((const float4*)x, out);
    }
}

// round 8
// speedup vs baseline: 1.0291x; 1.0291x over previous
#include <cuda_runtime.h>
#include <cuda_bf16.h>

// Problem constants (fixed by the reference)
#define BATCH 524288
#define NFEAT 8

#define TPB 256
#define NBLOCKS 592                      // 148 SMs * 4 blocks: one balanced wave
#define GT (NBLOCKS * TPB)               // 151552 grid threads
#define NFULL 3                          // full grid-strided passes
#define REM (BATCH - NFULL * GT)         // 69632 tail elements (pass 3, predicated)

// Contraction tensor (padded to 28 floats = 7 float4 for vector loads):
// out = sum_{a,b,c} T[a*9+b*3+c] * v0_a*v1_b*v2_c, v_i = (1, cos x_i, sin x_i)
__device__ float4 d_T4[7];

// ---------------- Setup kernel (1 block, 64 threads) ----------------
// Builds V (variational unitary), M = Re(V^H Z0 V), then T via three
// branch-free separable sweeps. Overlapped with the main kernel via PDL.
__global__ void vqc_setup_kernel(const float* __restrict__ w) {
    __shared__ float2 sc[18];
    __shared__ float Vr[8][8];
    __shared__ float Vi[8][8];
    __shared__ float Ms[8][8];
    __shared__ float Ps[48];
    __shared__ float Qs[36];

    const int tid = threadIdx.x;
    float* dT = (float*)d_T4;

    if (tid < 32) {
        if (tid < 18) {
            float c, s;
            __sincosf(0.5f * __ldg(&w[tid]), &s, &c);
            sc[tid] = make_float2(c, s);
        }
        __syncwarp();

        if (tid < 8) {
            float re[8], im[8];
#pragma unroll
            for (int k = 0; k < 8; k++) { re[k] = 0.0f; im[k] = 0.0f; }
            re[tid] = 1.0f;

#pragma unroll
            for (int l = 0; l < 3; l++) {
#pragma unroll
                for (int q = 0; q < 3; q++) {
                    const float2 y = sc[(l * 3 + q) * 2 + 0];
                    const float2 z = sc[(l * 3 + q) * 2 + 1];
                    const float cy = y.x, sy = y.y, cz = z.x, sz = z.y;
                    const int bit = 4 >> q;
#pragma unroll
                    for (int j = 0; j < 8; j++) {
                        if (j & bit) continue;
                        const int j1 = j | bit;
                        const float r0 = re[j],  i0 = im[j];
                        const float r1 = re[j1], i1 = im[j1];
                        // RY(th)
                        const float nr0 = cy * r0 - sy * r1;
                        const float ni0 = cy * i0 - sy * i1;
                        const float nr1 = sy * r0 + cy * r1;
                        const float ni1 = sy * i0 + cy * i1;
                        // RZ(ph)
                        re[j]  = cz * nr0 + sz * ni0;
                        im[j]  = cz * ni0 - sz * nr0;
                        re[j1] = cz * nr1 - sz * ni1;
                        im[j1] = cz * ni1 + sz * nr1;
                    }
                }
                // CNOT(0,1): control bit4, target bit2
#pragma unroll
                for (int j = 0; j < 8; j++) {
                    if ((j & 4) && !(j & 2)) {
                        const int j1 = j | 2;
                        float tmp;
                        tmp = re[j]; re[j] = re[j1]; re[j1] = tmp;
                        tmp = im[j]; im[j] = im[j1]; im[j1] = tmp;
                    }
                }
                // CNOT(1,2): control bit2, target bit1
#pragma unroll
                for (int j = 0; j < 8; j++) {
                    if ((j & 2) && !(j & 1)) {
                        const int j1 = j | 1;
                        float tmp;
                        tmp = re[j]; re[j] = re[j1]; re[j1] = tmp;
                        tmp = im[j]; im[j] = im[j1]; im[j1] = tmp;
                    }
                }
            }
#pragma unroll
            for (int r = 0; r < 8; r++) { Vr[r][tid] = re[r]; Vi[r][tid] = im[r]; }
        }
    }
    __syncthreads();

    if (tid < 64) {
        const int j = tid >> 3, k = tid & 7;
        float m = 0.0f;
#pragma unroll
        for (int r = 0; r < 8; r++) {
            const float zr = (r < 4) ? 1.0f : -1.0f;
            m += zr * (Vr[r][j] * Vr[r][k] + Vi[r][j] * Vi[r][k]);
        }
        Ms[j][k] = m;
    }
    __syncthreads();

    if (tid < 48) {  // Sweep 1 (qubit 0)
        const int a = tid >> 4, rem = tid & 15;
        const int r = rem >> 2, s = rem & 3;
        const float m00 = Ms[r][s],     m11 = Ms[4 + r][4 + s];
        const float m01 = Ms[r][4 + s], m10 = Ms[4 + r][s];
        float v;
        if (a == 0)      v = 0.5f * (m00 + m11);
        else if (a == 1) v = 0.5f * (m00 - m11);
        else             v = 0.5f * (m01 + m10);
        Ps[tid] = v;
    }
    __syncthreads();

    if (tid < 36) {  // Sweep 2 (qubit 1)
        const int a = tid / 12, rem = tid % 12;
        const int b = rem >> 2, j0 = (rem >> 1) & 1, k0 = rem & 1;
        const float* Pa = &Ps[a * 16];
        const float p00 = Pa[(0 * 2 + j0) * 4 + (0 * 2 + k0)];
        const float p11 = Pa[(1 * 2 + j0) * 4 + (1 * 2 + k0)];
        const float p01 = Pa[(0 * 2 + j0) * 4 + (1 * 2 + k0)];
        const float p10 = Pa[(1 * 2 + j0) * 4 + (0 * 2 + k0)];
        float v;
        if (b == 0)      v = 0.5f * (p00 + p11);
        else if (b == 1) v = 0.5f * (p00 - p11);
        else             v = 0.5f * (p01 + p10);
        Qs[tid] = v;
    }
    __syncthreads();

    if (tid < 28) {  // Sweep 3 (qubit 2) -> global T (pad slot 27 with 0)
        if (tid == 27) {
            dT[27] = 0.0f;
        } else {
            const int a = tid / 9, b = (tid / 3) % 3, c = tid % 3;
            const float* Qab = &Qs[a * 12 + b * 4];
            const float q00 = Qab[0], q01 = Qab[1], q10 = Qab[2], q11 = Qab[3];
            float v;
            if (c == 0)      v = 0.5f * (q00 + q11);
            else if (c == 1) v = 0.5f * (q00 - q11);
            else             v = 0.5f * (q01 + q10);
            dT[tid] = v;
        }
    }
}

// ---------------- Main kernel (PDL secondary, balanced single wave) ----------------
__global__ void __launch_bounds__(TPB, 4) vqc_main_kernel(
    const float4* __restrict__ x4, float* __restrict__ out) {

    const int gtid = blockIdx.x * TPB + threadIdx.x;
    const bool tail = gtid < REM;

    // Issue all batch loads FIRST — independent of the setup kernel's output,
    // overlapping both DRAM latency and the PDL wait. Grid-strided mapping:
    // every block does identical work (no straggler wave).
    float4 xv[NFULL + 1];
#pragma unroll
    for (int e = 0; e < NFULL; e++) {
        xv[e] = x4[2 * (gtid + e * GT)];   // first 16B of each 32B row
    }
    if (tail) xv[NFULL] = x4[2 * (gtid + NFULL * GT)];

#if __CUDA_ARCH__ >= 900
    // Wait for the setup kernel (PDL): only now is d_T4 guaranteed visible.
    cudaGridDependencySynchronize();
#endif

    // 7 uniform vector loads for the 27(+1 pad) coefficients.
    float T[28];
#pragma unroll
    for (int i = 0; i < 7; i++) {
        const float4 t = __ldg(&d_T4[i]);
        T[4 * i + 0] = t.x; T[4 * i + 1] = t.y;
        T[4 * i + 2] = t.z; T[4 * i + 3] = t.w;
    }

#pragma unroll
    for (int e = 0; e < NFULL + 1; e++) {
        if (e == NFULL && !tail) break;
        float c0, s0, c1, s1, c2, s2;
        __sincosf(xv[e].x, &s0, &c0);
        __sincosf(xv[e].y, &s1, &c1);
        __sincosf(xv[e].z, &s2, &c2);

        float u[3];
#pragma unroll
        for (int a = 0; a < 3; a++) {
            float wb[3];
#pragma unroll
            for (int b = 0; b < 3; b++) {
                const float* Tb = &T[a * 9 + b * 3];
                wb[b] = Tb[0] + Tb[1] * c2 + Tb[2] * s2;
            }
            u[a] = wb[0] + wb[1] * c1 + wb[2] * s1;
        }
        out[gtid + e * GT] = u[0] + u[1] * c0 + u[2] * s0;
    }
}

extern "C" void kernel_launch(void* const* d_in, const int* in_sizes, int n_in,
                              void* d_out, int out_size) {
    const float* x = (const float*)d_in[0];        // [BATCH, 8]
    const float* w = (const float*)d_in[1];        // [3, 3, 2]
    float* out = (float*)d_out;                    // [BATCH, 1]

    vqc_setup_kernel<<<1, 64>>>(w);

    // Launch main kernel with programmatic stream serialization (PDL):
    // its blocks may launch while the setup kernel is still running; the
    // in-kernel cudaGridDependencySynchronize() provides the ordering.
    cudaLaunchConfig_t cfg = {};
    cfg.gridDim = dim3(NBLOCKS, 1, 1);
    cfg.blockDim = dim3(TPB, 1, 1);
    cfg.dynamicSmemBytes = 0;
    cfg.stream = 0;  // legacy default stream (same as <<<>>>)

    cudaLaunchAttribute attr;
    attr.id = cudaLaunchAttributeProgrammaticStreamSerialization;
    attr.val.programmaticStreamSerializationAllowed = 1;
    cfg.attrs = &attr;
    cfg.numAttrs = 1;

    cudaError_t e = cudaLaunchKernelEx(&cfg, vqc_main_kernel,
                                       (const float4*)x, out);
    if (e != cudaSuccess) {
        // Fallback: plain stream-ordered launch (sync becomes a no-op).
        vqc_main_kernel<<<NBLOCKS, TPB>>>((const float4*)x, out);
    }
}

// round 9
// speedup vs baseline: 1.0679x; 1.0377x over previous
#include <cuda_runtime.h>
#include <cuda_bf16.h>

// Problem constants (fixed by the reference)
#define BATCH 524288
#define NFEAT 8

#define TPB 256
#define NBLOCKS 592                      // 148 SMs * 4 blocks: one balanced wave
#define GT (NBLOCKS * TPB)               // 151552 grid threads
#define NFULL 3                          // full grid-strided passes
#define REM (BATCH - NFULL * GT)         // 69632 tail elements (predicated 4th)

#define FULLMASK 0xFFFFFFFFu

// Single fused kernel. Warp 0 of each block computes the 27-coefficient
// contraction tensor T entirely with register math + warp shuffles (no
// internal barriers), while every warp's batch loads are already in flight.
// Then: out = sum_{a,b,c} T[a,b,c] * v0_a*v1_b*v2_c, v_i = (1, cos x_i, sin x_i).
__global__ void __launch_bounds__(TPB) vqc_kernel(
    const float4* __restrict__ x4, float* __restrict__ out,
    const float* __restrict__ w) {

    __shared__ float sT[28];

    const int tid = threadIdx.x;
    const int gtid = blockIdx.x * TPB + tid;
    const bool tail = gtid < REM;

    // ---- Issue all batch loads FIRST (independent LDG.128; grid-strided,
    // every block does identical work -> no straggler wave) ----
    float4 xv[NFULL + 1];
#pragma unroll
    for (int e = 0; e < NFULL; e++) {
        xv[e] = x4[2 * (gtid + e * GT)];   // first 16B of each 32B row
    }
    if (tail) xv[NFULL] = x4[2 * (gtid + NFULL * GT)];

    // ================= Warp 0: compute T via shuffles =================
    if (tid < 32) {
        const int lane = tid;

        // -- 18 half-angle sincos, one per lane (clamped index, no divergence) --
        float cw, sw;
        {
            const int wi = lane < 18 ? lane : 17;
            __sincosf(0.5f * __ldg(&w[wi]), &sw, &cw);
        }

        // -- Each lane simulates column `lane` of V (lanes >=8 compute junk,
        //    never read). Gate params fetched from the sincos lanes via shfl. --
        float re[8], im[8];
#pragma unroll
        for (int k = 0; k < 8; k++) {
            re[k] = (k == lane) ? 1.0f : 0.0f;
            im[k] = 0.0f;
        }

#pragma unroll
        for (int l = 0; l < 3; l++) {
#pragma unroll
            for (int q = 0; q < 3; q++) {
                const int g = l * 3 + q;
                const float cy = __shfl_sync(FULLMASK, cw, 2 * g);
                const float sy = __shfl_sync(FULLMASK, sw, 2 * g);
                const float cz = __shfl_sync(FULLMASK, cw, 2 * g + 1);
                const float sz = __shfl_sync(FULLMASK, sw, 2 * g + 1);
                const int bit = 4 >> q;  // qubit q occupies bit (2-q)
#pragma unroll
                for (int j = 0; j < 8; j++) {
                    if (j & bit) continue;
                    const int j1 = j | bit;
                    const float r0 = re[j],  i0 = im[j];
                    const float r1 = re[j1], i1 = im[j1];
                    // RY(th)
                    const float nr0 = cy * r0 - sy * r1;
                    const float ni0 = cy * i0 - sy * i1;
                    const float nr1 = sy * r0 + cy * r1;
                    const float ni1 = sy * i0 + cy * i1;
                    // RZ(ph): amp(bit=0) *= cz - i sz ; amp(bit=1) *= cz + i sz
                    re[j]  = cz * nr0 + sz * ni0;
                    im[j]  = cz * ni0 - sz * nr0;
                    re[j1] = cz * nr1 - sz * ni1;
                    im[j1] = cz * ni1 + sz * nr1;
                }
            }
            // CNOT(0,1): control bit4, target bit2
#pragma unroll
            for (int j = 0; j < 8; j++) {
                if ((j & 4) && !(j & 2)) {
                    const int j1 = j | 2;
                    float tmp;
                    tmp = re[j]; re[j] = re[j1]; re[j1] = tmp;
                    tmp = im[j]; im[j] = im[j1]; im[j1] = tmp;
                }
            }
            // CNOT(1,2): control bit2, target bit1
#pragma unroll
            for (int j = 0; j < 8; j++) {
                if ((j & 2) && !(j & 1)) {
                    const int j1 = j | 1;
                    float tmp;
                    tmp = re[j]; re[j] = re[j1]; re[j1] = tmp;
                    tmp = im[j]; im[j] = im[j1]; im[j1] = tmp;
                }
            }
        }

        // -- M = Re(V^H Z0 V): lane holds m0 = M[j0][k0], m1 = M[j0+4][k0],
        //    j0 = lane>>3 (0..3), k0 = lane&7. Column c of V lives in lane c. --
        const int j0 = lane >> 3, k0 = lane & 7;
        float m0 = 0.0f, m1 = 0.0f;
#pragma unroll
        for (int r = 0; r < 8; r++) {
            const float arj  = __shfl_sync(FULLMASK, re[r], j0);
            const float aij  = __shfl_sync(FULLMASK, im[r], j0);
            const float arj4 = __shfl_sync(FULLMASK, re[r], j0 + 4);
            const float aij4 = __shfl_sync(FULLMASK, im[r], j0 + 4);
            const float ark  = __shfl_sync(FULLMASK, re[r], k0);
            const float aik  = __shfl_sync(FULLMASK, im[r], k0);
            const float zr = (r < 4) ? 1.0f : -1.0f;
            m0 += zr * (arj  * ark + aij  * aik);
            m1 += zr * (arj4 * ark + aij4 * aik);
        }

        // -- T[a,b,c] (lane t<27): signed 8-term sum of M entries.
        //    Per qubit basis x, term choice i: j-bit = i, k-bit = i^(x==2),
        //    sign = -1 iff (x==1 && i==1). Weight (0.5)^3 = 0.125. --
        const int a = lane / 9, b = (lane / 3) % 3, c = lane % 3;
        const int fa = (a == 2), fb = (b == 2), fc = (c == 2);
        const int na = (a == 1), nb = (b == 1), nc = (c == 1);
        float acc = 0.0f;
#pragma unroll
        for (int i0 = 0; i0 < 2; i0++)
#pragma unroll
            for (int i1 = 0; i1 < 2; i1++)
#pragma unroll
                for (int i2 = 0; i2 < 2; i2++) {
                    const int j = (i0 << 2) | (i1 << 1) | i2;
                    const int k = ((i0 ^ fa) << 2) | ((i1 ^ fb) << 1) | (i2 ^ fc);
                    const int idx = j * 8 + k;
                    const float v0 = __shfl_sync(FULLMASK, m0, idx & 31);
                    const float v1 = __shfl_sync(FULLMASK, m1, idx & 31);
                    const float mv = i0 ? v1 : v0;  // idx>=32 <=> j>=4 <=> i0
                    const int neg = (na & i0) ^ (nb & i1) ^ (nc & i2);
                    acc += neg ? -mv : mv;
                }

        if (lane < 27) sT[lane] = 0.125f * acc;
        if (lane == 27) sT[27] = 0.0f;
    }
    __syncthreads();

    // ================= Main compute: 3.46 elements/thread =================
    float T[27];
#pragma unroll
    for (int i = 0; i < 27; i++) T[i] = sT[i];

#pragma unroll
    for (int e = 0; e < NFULL + 1; e++) {
        if (e == NFULL && !tail) break;
        float c0, s0, c1, s1, c2, s2;
        __sincosf(xv[e].x, &s0, &c0);
        __sincosf(xv[e].y, &s1, &c1);
        __sincosf(xv[e].z, &s2, &c2);

        float u[3];
#pragma unroll
        for (int a2 = 0; a2 < 3; a2++) {
            float wb[3];
#pragma unroll
            for (int b2 = 0; b2 < 3; b2++) {
                const float* Tb = &T[a2 * 9 + b2 * 3];
                wb[b2] = Tb[0] + Tb[1] * c2 + Tb[2] * s2;
            }
            u[a2] = wb[0] + wb[1] * c1 + wb[2] * s1;
        }
        out[gtid + e * GT] = u[0] + u[1] * c0 + u[2] * s0;
    }
}

extern "C" void kernel_launch(void* const* d_in, const int* in_sizes, int n_in,
                              void* d_out, int out_size) {
    const float* x = (const float*)d_in[0];        // [BATCH, 8]
    const float* w = (const float*)d_in[1];        // [3, 3, 2]
    float* out = (float*)d_out;                    // [BATCH, 1]

    vqc_kernel<<<NBLOCKS, TPB>>>((const float4*)x, out, w);
}